// round 8
// baseline (speedup 1.0000x reference)
#include <cuda_runtime.h>
#include <cuda_fp16.h>
#include <cstddef>

#define N_NODES 50000
#define D 128
#define E_EDGES 800000
#define SCAN_BLK 1024
#define SCAN_NB ((N_NODES + SCAN_BLK - 1) / SCAN_BLK)   // 49

// Scratch (no allocations allowed in kernel_launch)
__device__ float  d_agg[(size_t)N_NODES * D];   // mean-aggregated features (fp32)
__device__ float  d_h[(size_t)N_NODES * D];     // layer-1 output (fp32)
__device__ __half d_xh[(size_t)N_NODES * D];    // fp16 copy of x   (gather source, layer 1)
__device__ __half d_hh[(size_t)N_NODES * D];    // fp16 copy of h   (gather source, layer 2)
__device__ int    d_deg[N_NODES];
__device__ int    d_rowptr[N_NODES + 1];
__device__ int    d_cursor[N_NODES + 1];
__device__ int    d_adj[E_EDGES];               // src ids grouped by dst
__device__ int    d_bsum[64];
__device__ int    d_boff[64];
__device__ float  d_wt1[256 * 128];             // combined [Wl1;Wr1] transposed: wt[k][j]
__device__ float  d_wt2[256 * 128];

// ---------------------------------------------------------------------------
__global__ void zero_deg_kernel() {
    int i = blockIdx.x * blockDim.x + threadIdx.x;
    if (i < N_NODES) d_deg[i] = 0;
}

__global__ void count_kernel(const int* __restrict__ dst) {
    int stride = gridDim.x * blockDim.x;
    for (int e = blockIdx.x * blockDim.x + threadIdx.x; e < E_EDGES; e += stride) {
        atomicAdd(&d_deg[dst[e]], 1);
    }
}

// intra-block inclusive scan (warp-shuffle based) -> rowptr[i+1]; block sums -> d_bsum
__global__ void scan1_kernel() {
    __shared__ int wsum[32];
    int i = blockIdx.x * SCAN_BLK + threadIdx.x;
    int lane = threadIdx.x & 31;
    int warp = threadIdx.x >> 5;
    int v = (i < N_NODES) ? d_deg[i] : 0;
    int s = v;
#pragma unroll
    for (int off = 1; off < 32; off <<= 1) {
        int t = __shfl_up_sync(0xffffffffu, s, off);
        if (lane >= off) s += t;
    }
    if (lane == 31) wsum[warp] = s;
    __syncthreads();
    if (warp == 0) {
        int w = wsum[lane];
#pragma unroll
        for (int off = 1; off < 32; off <<= 1) {
            int t = __shfl_up_sync(0xffffffffu, w, off);
            if (lane >= off) w += t;
        }
        wsum[lane] = w;
    }
    __syncthreads();
    int incl = s + (warp > 0 ? wsum[warp - 1] : 0);
    if (i < N_NODES) d_rowptr[i + 1] = incl;
    if (threadIdx.x == SCAN_BLK - 1) d_bsum[blockIdx.x] = incl;
}

// exclusive scan of the 49 block sums (single block, 64 threads)
__global__ void scan2_kernel() {
    __shared__ int sh[64];
    int t = threadIdx.x;
    int v = (t < SCAN_NB) ? d_bsum[t] : 0;
    sh[t] = v;
    __syncthreads();
#pragma unroll
    for (int off = 1; off < 64; off <<= 1) {
        int u = (t >= off) ? sh[t - off] : 0;
        __syncthreads();
        sh[t] += u;
        __syncthreads();
    }
    d_boff[t] = sh[t] - v;   // exclusive
}

// finalize rowptr and seed fill cursors
__global__ void scan3_kernel() {
    int i = blockIdx.x * blockDim.x + threadIdx.x;
    if (i == 0) { d_rowptr[0] = 0; d_cursor[0] = 0; }
    if (i < N_NODES) {
        int r = d_rowptr[i + 1] + d_boff[i >> 10];
        d_rowptr[i + 1] = r;
        d_cursor[i + 1] = r;
    }
}

__global__ void fill_kernel(const int* __restrict__ src, const int* __restrict__ dst) {
    int stride = gridDim.x * blockDim.x;
    for (int e = blockIdx.x * blockDim.x + threadIdx.x; e < E_EDGES; e += stride) {
        int d = dst[e];
        int p = atomicAdd(&d_cursor[d], 1);
        d_adj[p] = src[e];
    }
}

// wt[k*128+j]: k<128 -> Wl[j][k]; k>=128 -> Wr[j][k-128]
__global__ void prep_kernel(const float* __restrict__ Wl1, const float* __restrict__ Wr1,
                            const float* __restrict__ Wl2, const float* __restrict__ Wr2) {
    int stride = gridDim.x * blockDim.x;
    for (int i = blockIdx.x * blockDim.x + threadIdx.x; i < 256 * 128; i += stride) {
        int k = i >> 7;
        int j = i & 127;
        if (k < 128) {
            d_wt1[i] = Wl1[j * 128 + k];
            d_wt2[i] = Wl2[j * 128 + k];
        } else {
            d_wt1[i] = Wr1[j * 128 + (k - 128)];
            d_wt2[i] = Wr2[j * 128 + (k - 128)];
        }
    }
}

// fp32 x -> fp16 d_xh (one-time per call)
__global__ void convert_x_kernel(const float* __restrict__ x) {
    int stride = gridDim.x * blockDim.x;
    size_t total = (size_t)N_NODES * D / 4;
    for (size_t t = blockIdx.x * blockDim.x + threadIdx.x; t < total; t += stride) {
        float4 v = *(const float4*)(x + t * 4);
        __half2 a = __floats2half2_rn(v.x, v.y);
        __half2 b = __floats2half2_rn(v.z, v.w);
        __half2* p = (__half2*)(d_xh + t * 4);
        p[0] = a;
        p[1] = b;
    }
}

// One warp per node: sum neighbor rows from the fp16 copy (8B/lane/neighbor),
// accumulate fp32, scale by 1/deg, store fp32. 4-wide unroll for MLP.
__global__ void __launch_bounds__(256) gather_kernel(int layer) {
    const __half* __restrict__ xin = (layer == 0) ? d_xh : d_hh;
    int gid = blockIdx.x * blockDim.x + threadIdx.x;
    int n = gid >> 5;
    if (n >= N_NODES) return;
    int lane = gid & 31;
    int base = d_rowptr[n];
    int end  = d_rowptr[n + 1];
    int deg  = end - base;
    size_t feat = (size_t)lane * 4;   // 4 halves per lane

    float4 acc = make_float4(0.f, 0.f, 0.f, 0.f);
    for (int i = base; i < end; i += 32) {
        int cnt = min(32, end - i);
        int sidx = (lane < cnt) ? __ldg(d_adj + i + lane) : 0;
        int j = 0;
        for (; j + 4 <= cnt; j += 4) {
            int s0 = __shfl_sync(0xffffffffu, sidx, j);
            int s1 = __shfl_sync(0xffffffffu, sidx, j + 1);
            int s2 = __shfl_sync(0xffffffffu, sidx, j + 2);
            int s3 = __shfl_sync(0xffffffffu, sidx, j + 3);
            uint2 r0 = *(const uint2*)(xin + (size_t)s0 * D + feat);
            uint2 r1 = *(const uint2*)(xin + (size_t)s1 * D + feat);
            uint2 r2 = *(const uint2*)(xin + (size_t)s2 * D + feat);
            uint2 r3 = *(const uint2*)(xin + (size_t)s3 * D + feat);
            float2 a0 = __half22float2(*(__half2*)&r0.x), b0 = __half22float2(*(__half2*)&r0.y);
            float2 a1 = __half22float2(*(__half2*)&r1.x), b1 = __half22float2(*(__half2*)&r1.y);
            float2 a2 = __half22float2(*(__half2*)&r2.x), b2 = __half22float2(*(__half2*)&r2.y);
            float2 a3 = __half22float2(*(__half2*)&r3.x), b3 = __half22float2(*(__half2*)&r3.y);
            acc.x += (a0.x + a1.x) + (a2.x + a3.x);
            acc.y += (a0.y + a1.y) + (a2.y + a3.y);
            acc.z += (b0.x + b1.x) + (b2.x + b3.x);
            acc.w += (b0.y + b1.y) + (b2.y + b3.y);
        }
        for (; j < cnt; j++) {
            int s = __shfl_sync(0xffffffffu, sidx, j);
            uint2 r = *(const uint2*)(xin + (size_t)s * D + feat);
            float2 a = __half22float2(*(__half2*)&r.x);
            float2 b = __half22float2(*(__half2*)&r.y);
            acc.x += a.x; acc.y += a.y; acc.z += b.x; acc.w += b.y;
        }
    }
    float sc = 1.0f / fmaxf((float)deg, 1.0f);
    acc.x *= sc; acc.y *= sc; acc.z *= sc; acc.w *= sc;
    *(float4*)(d_agg + (size_t)n * D + feat) = acc;
}

// Fused: out[n][j] = sum_{k<128} agg[n][k]*wt[k][j] + sum_{k>=128} xin[n][k-128]*wt[k][j] + b[j]
// SGEMM: BM=128, BN=128, BK=16, 256 threads, 8x8 microtile, double-buffered shared.
// layer==0 additionally stores the output as fp16 into d_hh (gather source for layer 2).
__global__ void __launch_bounds__(256) gemm_kernel(const float* __restrict__ x,
                                                   const float* __restrict__ bias,
                                                   float* __restrict__ outp,
                                                   int layer) {
    const float* __restrict__ wt  = (layer == 0) ? d_wt1 : d_wt2;
    const float* __restrict__ xin = (layer == 0) ? x : d_h;
    float* __restrict__ out       = (layer == 0) ? d_h : outp;

    __shared__ float As[2][16][132];   // [buf][k][m]
    __shared__ float Bs[2][16][128];   // [buf][k][j]

    int tid = threadIdx.x;
    int block_row0 = blockIdx.x * 128;
    int rowg = (tid >> 4) * 8;
    int colg = (tid & 15) * 8;

    float acc[8][8];
#pragma unroll
    for (int i = 0; i < 8; i++)
#pragma unroll
        for (int j = 0; j < 8; j++) acc[i][j] = 0.0f;

    float4 va[2], vb[2];

    // ---- prefetch tile 0 into registers ----
#pragma unroll
    for (int p = 0; p < 2; p++) {
        int idx = tid + p * 256;
        int r = idx >> 2;
        int kq = (idx & 3) * 4;
        int gr = block_row0 + r;
        int grc = (gr < N_NODES) ? gr : (N_NODES - 1);
        va[p] = *(const float4*)(d_agg + (size_t)grc * D + 0 + kq);
        int k = idx >> 5;
        int j = (idx & 31) * 4;
        vb[p] = *(const float4*)(wt + (size_t)(0 + k) * 128 + j);
    }
    // store tile 0
#pragma unroll
    for (int p = 0; p < 2; p++) {
        int idx = tid + p * 256;
        int r = idx >> 2;
        int kq = (idx & 3) * 4;
        As[0][kq + 0][r] = va[p].x;
        As[0][kq + 1][r] = va[p].y;
        As[0][kq + 2][r] = va[p].z;
        As[0][kq + 3][r] = va[p].w;
        int k = idx >> 5;
        int j = (idx & 31) * 4;
        *(float4*)&Bs[0][k][j] = vb[p];
    }
    __syncthreads();

#pragma unroll
    for (int t = 0; t < 16; t++) {
        int buf = t & 1;
        // prefetch tile t+1
        if (t < 15) {
            int kt = (t + 1) * 16;
            const float* __restrict__ asrc = (kt < 128) ? d_agg : xin;
            int kbase = (kt < 128) ? kt : (kt - 128);
#pragma unroll
            for (int p = 0; p < 2; p++) {
                int idx = tid + p * 256;
                int r = idx >> 2;
                int kq = (idx & 3) * 4;
                int gr = block_row0 + r;
                int grc = (gr < N_NODES) ? gr : (N_NODES - 1);
                va[p] = *(const float4*)(asrc + (size_t)grc * D + kbase + kq);
                int k = idx >> 5;
                int j = (idx & 31) * 4;
                vb[p] = *(const float4*)(wt + (size_t)(kt + k) * 128 + j);
            }
        }
        // compute on current buffer
#pragma unroll
        for (int k = 0; k < 16; k++) {
            float4 a0 = *(const float4*)&As[buf][k][rowg];
            float4 a1 = *(const float4*)&As[buf][k][rowg + 4];
            float4 b0 = *(const float4*)&Bs[buf][k][colg];
            float4 b1 = *(const float4*)&Bs[buf][k][colg + 4];
            float a[8] = {a0.x, a0.y, a0.z, a0.w, a1.x, a1.y, a1.z, a1.w};
            float b[8] = {b0.x, b0.y, b0.z, b0.w, b1.x, b1.y, b1.z, b1.w};
#pragma unroll
            for (int i = 0; i < 8; i++)
#pragma unroll
                for (int j = 0; j < 8; j++)
                    acc[i][j] += a[i] * b[j];
        }
        // store prefetched tile into other buffer
        if (t < 15) {
#pragma unroll
            for (int p = 0; p < 2; p++) {
                int idx = tid + p * 256;
                int r = idx >> 2;
                int kq = (idx & 3) * 4;
                As[buf ^ 1][kq + 0][r] = va[p].x;
                As[buf ^ 1][kq + 1][r] = va[p].y;
                As[buf ^ 1][kq + 2][r] = va[p].z;
                As[buf ^ 1][kq + 3][r] = va[p].w;
                int k = idx >> 5;
                int j = (idx & 31) * 4;
                *(float4*)&Bs[buf ^ 1][k][j] = vb[p];
            }
        }
        __syncthreads();
    }

    // ---- epilogue: add bias, store (+ fp16 copy for layer 0) ----
    float bb[8];
#pragma unroll
    for (int j = 0; j < 8; j++) bb[j] = __ldg(bias + colg + j);
#pragma unroll
    for (int i = 0; i < 8; i++) {
        int gr = block_row0 + rowg + i;
        if (gr < N_NODES) {
            float4 o0, o1;
            o0.x = acc[i][0] + bb[0]; o0.y = acc[i][1] + bb[1];
            o0.z = acc[i][2] + bb[2]; o0.w = acc[i][3] + bb[3];
            o1.x = acc[i][4] + bb[4]; o1.y = acc[i][5] + bb[5];
            o1.z = acc[i][6] + bb[6]; o1.w = acc[i][7] + bb[7];
            *(float4*)(out + (size_t)gr * D + colg)     = o0;
            *(float4*)(out + (size_t)gr * D + colg + 4) = o1;
            if (layer == 0) {
                __half2* ph = (__half2*)(d_hh + (size_t)gr * D + colg);
                ph[0] = __floats2half2_rn(o0.x, o0.y);
                ph[1] = __floats2half2_rn(o0.z, o0.w);
                ph[2] = __floats2half2_rn(o1.x, o1.y);
                ph[3] = __floats2half2_rn(o1.z, o1.w);
            }
        }
    }
}

// ---------------------------------------------------------------------------
extern "C" void kernel_launch(void* const* d_in, const int* in_sizes, int n_in,
                              void* d_out, int out_size) {
    const float* x   = (const float*)d_in[0];
    const int*   ei  = (const int*)d_in[1];
    const float* Wl1 = (const float*)d_in[2];
    const float* bl1 = (const float*)d_in[3];
    const float* Wr1 = (const float*)d_in[4];
    const float* Wl2 = (const float*)d_in[5];
    const float* bl2 = (const float*)d_in[6];
    const float* Wr2 = (const float*)d_in[7];
    float* out = (float*)d_out;

    const int* src = ei;
    const int* dst = ei + E_EDGES;

    const int gather_blocks = (N_NODES * 32 + 255) / 256;
    const int gemm_blocks   = (N_NODES + 127) / 128;

    // ---- CSR build + fp16 feature copy (shared across both layers) ----
    zero_deg_kernel<<<(N_NODES + 255) / 256, 256>>>();
    count_kernel<<<(E_EDGES + 511) / 512, 256>>>(dst);
    scan1_kernel<<<SCAN_NB, SCAN_BLK>>>();
    scan2_kernel<<<1, 64>>>();
    scan3_kernel<<<(N_NODES + 255) / 256, 256>>>();
    fill_kernel<<<(E_EDGES + 511) / 512, 256>>>(src, dst);
    prep_kernel<<<128, 256>>>(Wl1, Wr1, Wl2, Wr2);
    convert_x_kernel<<<512, 256>>>(x);

    // ---- layer 1 ----
    gather_kernel<<<gather_blocks, 256>>>(0);
    gemm_kernel<<<gemm_blocks, 256>>>(x, bl1, nullptr, 0);

    // ---- layer 2 ----
    gather_kernel<<<gather_blocks, 256>>>(1);
    gemm_kernel<<<gemm_blocks, 256>>>(x, bl2, out, 1);
}

// round 10
// speedup vs baseline: 1.4275x; 1.4275x over previous
#include <cuda_runtime.h>
#include <cuda_fp16.h>
#include <mma.h>
#include <cstdint>
#include <cstddef>

using namespace nvcuda;

#define N_NODES 50000
#define D 128
#define E_EDGES 800000
#define SCAN_BLK 1024
#define SCAN_NB ((N_NODES + SCAN_BLK - 1) / SCAN_BLK)   // 49
#define FULL_TILES (N_NODES / 128)                       // 390
#define TAIL_ROW0 (FULL_TILES * 128)                     // 49920

// wmma kernel shared layout (dynamic)
#define LDA 264                                  // 256 + 8 pad (halves)
#define SM_AS 0
#define SM_BS (128 * LDA * 2)                    // 67584
#define SM_BIAS (SM_BS + 128 * LDA * 2)          // 135168
#define SM_TOTAL (SM_BIAS + 16 * 136 * 4)        // 143872

// Scratch (no allocations allowed in kernel_launch)
__device__ float  d_agg[(size_t)N_NODES * D];
__device__ float  d_h[(size_t)N_NODES * D];
__device__ int    d_deg[N_NODES];
__device__ int    d_rowptr[N_NODES + 1];
__device__ int    d_cursor[N_NODES + 1];
__device__ int    d_adj[E_EDGES];
__device__ int    d_bsum[64];
__device__ int    d_boff[64];
__device__ float  d_wt1[256 * 128];      // fp32 [k][j] (tail kernel)
__device__ float  d_wt2[256 * 128];
__device__ __half d_wt1h[128 * 256];     // fp16 [n][k] (wmma B)
__device__ __half d_wt2h[128 * 256];

// ---------------------------------------------------------------------------
__global__ void zero_deg_kernel() {
    int i = blockIdx.x * blockDim.x + threadIdx.x;
    if (i < N_NODES) d_deg[i] = 0;
}

__global__ void count_kernel(const int* __restrict__ dst) {
    int stride = gridDim.x * blockDim.x;
    for (int e = blockIdx.x * blockDim.x + threadIdx.x; e < E_EDGES; e += stride) {
        atomicAdd(&d_deg[dst[e]], 1);
    }
}

__global__ void scan1_kernel() {
    __shared__ int wsum[32];
    int i = blockIdx.x * SCAN_BLK + threadIdx.x;
    int lane = threadIdx.x & 31;
    int warp = threadIdx.x >> 5;
    int v = (i < N_NODES) ? d_deg[i] : 0;
    int s = v;
#pragma unroll
    for (int off = 1; off < 32; off <<= 1) {
        int t = __shfl_up_sync(0xffffffffu, s, off);
        if (lane >= off) s += t;
    }
    if (lane == 31) wsum[warp] = s;
    __syncthreads();
    if (warp == 0) {
        int w = wsum[lane];
#pragma unroll
        for (int off = 1; off < 32; off <<= 1) {
            int t = __shfl_up_sync(0xffffffffu, w, off);
            if (lane >= off) w += t;
        }
        wsum[lane] = w;
    }
    __syncthreads();
    int incl = s + (warp > 0 ? wsum[warp - 1] : 0);
    if (i < N_NODES) d_rowptr[i + 1] = incl;
    if (threadIdx.x == SCAN_BLK - 1) d_bsum[blockIdx.x] = incl;
}

__global__ void scan2_kernel() {
    __shared__ int sh[64];
    int t = threadIdx.x;
    int v = (t < SCAN_NB) ? d_bsum[t] : 0;
    sh[t] = v;
    __syncthreads();
#pragma unroll
    for (int off = 1; off < 64; off <<= 1) {
        int u = (t >= off) ? sh[t - off] : 0;
        __syncthreads();
        sh[t] += u;
        __syncthreads();
    }
    d_boff[t] = sh[t] - v;
}

__global__ void scan3_kernel() {
    int i = blockIdx.x * blockDim.x + threadIdx.x;
    if (i == 0) { d_rowptr[0] = 0; d_cursor[0] = 0; }
    if (i < N_NODES) {
        int r = d_rowptr[i + 1] + d_boff[i >> 10];
        d_rowptr[i + 1] = r;
        d_cursor[i + 1] = r;
    }
}

__global__ void fill_kernel(const int* __restrict__ src, const int* __restrict__ dst) {
    int stride = gridDim.x * blockDim.x;
    for (int e = blockIdx.x * blockDim.x + threadIdx.x; e < E_EDGES; e += stride) {
        int d = dst[e];
        int p = atomicAdd(&d_cursor[d], 1);
        d_adj[p] = src[e];
    }
}

// fp32 wt [k][j] for tail; fp16 wt [n][k] for wmma (k<128: Wl, else Wr)
__global__ void prep_kernel(const float* __restrict__ Wl1, const float* __restrict__ Wr1,
                            const float* __restrict__ Wl2, const float* __restrict__ Wr2) {
    int stride = gridDim.x * blockDim.x;
    for (int i = blockIdx.x * blockDim.x + threadIdx.x; i < 256 * 128; i += stride) {
        int k = i >> 7;
        int j = i & 127;
        float v1, v2;
        if (k < 128) {
            v1 = Wl1[j * 128 + k];
            v2 = Wl2[j * 128 + k];
        } else {
            v1 = Wr1[j * 128 + (k - 128)];
            v2 = Wr2[j * 128 + (k - 128)];
        }
        d_wt1[i] = v1;
        d_wt2[i] = v2;
        d_wt1h[j * 256 + k] = __float2half(v1);   // [n][k]
        d_wt2h[j * 256 + k] = __float2half(v2);
    }
}

// One warp per node: sum neighbor fp32 rows, scale by 1/deg, store (R7-proven).
__global__ void __launch_bounds__(256) gather_kernel(const float* __restrict__ x, int layer) {
    const float* __restrict__ xin = (layer == 0) ? x : d_h;
    int gid = blockIdx.x * blockDim.x + threadIdx.x;
    int n = gid >> 5;
    if (n >= N_NODES) return;
    int lane = gid & 31;
    int base = d_rowptr[n];
    int end  = d_rowptr[n + 1];
    int deg  = end - base;
    size_t feat = (size_t)lane * 4;

    float4 acc = make_float4(0.f, 0.f, 0.f, 0.f);
    for (int i = base; i < end; i += 32) {
        int cnt = min(32, end - i);
        int sidx = (lane < cnt) ? __ldg(d_adj + i + lane) : 0;
        int j = 0;
        for (; j + 4 <= cnt; j += 4) {
            int s0 = __shfl_sync(0xffffffffu, sidx, j);
            int s1 = __shfl_sync(0xffffffffu, sidx, j + 1);
            int s2 = __shfl_sync(0xffffffffu, sidx, j + 2);
            int s3 = __shfl_sync(0xffffffffu, sidx, j + 3);
            float4 v0 = *(const float4*)(xin + (size_t)s0 * D + feat);
            float4 v1 = *(const float4*)(xin + (size_t)s1 * D + feat);
            float4 v2 = *(const float4*)(xin + (size_t)s2 * D + feat);
            float4 v3 = *(const float4*)(xin + (size_t)s3 * D + feat);
            acc.x += (v0.x + v1.x) + (v2.x + v3.x);
            acc.y += (v0.y + v1.y) + (v2.y + v3.y);
            acc.z += (v0.z + v1.z) + (v2.z + v3.z);
            acc.w += (v0.w + v1.w) + (v2.w + v3.w);
        }
        for (; j < cnt; j++) {
            int s = __shfl_sync(0xffffffffu, sidx, j);
            float4 v = *(const float4*)(xin + (size_t)s * D + feat);
            acc.x += v.x; acc.y += v.y; acc.z += v.z; acc.w += v.w;
        }
    }
    float sc = 1.0f / fmaxf((float)deg, 1.0f);
    acc.x *= sc; acc.y *= sc; acc.z *= sc; acc.w *= sc;
    *(float4*)(d_agg + (size_t)n * D + feat) = acc;
}

// ---------------------------------------------------------------------------
// wmma fp16 GEMM (full 128-row tiles): D[128,128] = Ah[128,256] @ Bh[128,256]^T + bias
// Whole A and B tiles staged in shared once; one sync; 16 uninterrupted k-steps.
__global__ void __launch_bounds__(256) gemm_wmma_kernel(const float* __restrict__ x,
                                                        const float* __restrict__ bias,
                                                        float* __restrict__ outp,
                                                        int layer) {
    extern __shared__ char smem[];
    const float* __restrict__ xin = (layer == 0) ? x : d_h;
    float* __restrict__ out       = (layer == 0) ? d_h : outp;
    const __half* __restrict__ wth = (layer == 0) ? d_wt1h : d_wt2h;

    __half (*As)[LDA]   = (__half(*)[LDA])(smem + SM_AS);
    __half (*Bs)[LDA]   = (__half(*)[LDA])(smem + SM_BS);
    float  (*BiasSh)[136] = (float(*)[136])(smem + SM_BIAS);

    int tid = threadIdx.x;
    int wid = tid >> 5;
    int warp_m = (wid & 3) * 32;     // 0,32,64,96
    int warp_n = (wid >> 2) * 64;    // 0,64
    int block_row0 = blockIdx.x * 128;

    // ---- stage A: fp32 [agg|xin] -> fp16 shared, 4 fp32 per thread-iter ----
    for (int idx = tid; idx < 128 * 64; idx += 256) {   // 64 groups of 4 per row
        int m = idx >> 6;
        int kq = (idx & 63) * 4;
        const float* srcp = (kq < 128) ? (d_agg + (size_t)(block_row0 + m) * D + kq)
                                       : (xin + (size_t)(block_row0 + m) * D + (kq - 128));
        float4 v = *(const float4*)srcp;
        __half2 p0 = __floats2half2_rn(v.x, v.y);
        __half2 p1 = __floats2half2_rn(v.z, v.w);
        uint2 u;
        u.x = *(uint32_t*)&p0;
        u.y = *(uint32_t*)&p1;
        *(uint2*)&As[m][kq] = u;
    }
    // ---- stage B: fp16 [n][256] -> shared (8 halves per thread-iter) ----
    for (int idx = tid; idx < 128 * 32; idx += 256) {   // 32 uint4 per row
        int n = idx >> 5;
        int kq = (idx & 31) * 8;
        *(uint4*)&Bs[n][kq] = *(const uint4*)(wth + (size_t)n * 256 + kq);
    }
    // ---- bias broadcast tile (16 rows x 128) ----
    for (int i = tid; i < 16 * 128; i += 256) {
        BiasSh[i >> 7][i & 127] = __ldg(bias + (i & 127));
    }
    __syncthreads();

    // ---- accumulators initialized to bias ----
    wmma::fragment<wmma::accumulator, 16, 16, 16, float> c[2][4];
#pragma unroll
    for (int i = 0; i < 2; i++)
#pragma unroll
        for (int j = 0; j < 4; j++)
            wmma::load_matrix_sync(c[i][j], &BiasSh[0][warp_n + j * 16], 136,
                                   wmma::mem_row_major);

    // ---- mainloop: 16 k-steps, no syncs ----
#pragma unroll
    for (int k0 = 0; k0 < 256; k0 += 16) {
        wmma::fragment<wmma::matrix_a, 16, 16, 16, __half, wmma::row_major> a[2];
        wmma::fragment<wmma::matrix_b, 16, 16, 16, __half, wmma::col_major> b[4];
#pragma unroll
        for (int i = 0; i < 2; i++)
            wmma::load_matrix_sync(a[i], &As[warp_m + i * 16][k0], LDA);
#pragma unroll
        for (int j = 0; j < 4; j++)
            wmma::load_matrix_sync(b[j], &Bs[warp_n + j * 16][k0], LDA);
#pragma unroll
        for (int i = 0; i < 2; i++)
#pragma unroll
            for (int j = 0; j < 4; j++)
                wmma::mma_sync(c[i][j], a[i], b[j], c[i][j]);
    }

    // ---- store (all rows valid: full tiles only) ----
#pragma unroll
    for (int i = 0; i < 2; i++)
#pragma unroll
        for (int j = 0; j < 4; j++)
            wmma::store_matrix_sync(
                out + (size_t)(block_row0 + warp_m + i * 16) * D + warp_n + j * 16,
                c[i][j], D, wmma::mem_row_major);
}

// Guarded FFMA GEMM for the 80-row tail (rows >= TAIL_ROW0). R5-proven.
__global__ void __launch_bounds__(256) gemm_tail_kernel(const float* __restrict__ x,
                                                        const float* __restrict__ bias,
                                                        float* __restrict__ outp,
                                                        int layer) {
    const float* __restrict__ wt  = (layer == 0) ? d_wt1 : d_wt2;
    const float* __restrict__ xin = (layer == 0) ? x : d_h;
    float* __restrict__ out       = (layer == 0) ? d_h : outp;

    __shared__ float As[16][132];
    __shared__ float Bs[16][128];

    int tid = threadIdx.x;
    int block_row0 = TAIL_ROW0;
    int rowg = (tid >> 4) * 8;
    int colg = (tid & 15) * 8;

    float acc[8][8];
#pragma unroll
    for (int i = 0; i < 8; i++)
#pragma unroll
        for (int j = 0; j < 8; j++) acc[i][j] = 0.0f;

    for (int kt = 0; kt < 256; kt += 16) {
        const float* __restrict__ asrc = (kt < 128) ? d_agg : xin;
        int kbase = (kt < 128) ? kt : (kt - 128);
#pragma unroll
        for (int p = 0; p < 2; p++) {
            int idx = tid + p * 256;
            int r = idx >> 2;
            int kq = (idx & 3) * 4;
            int gr = block_row0 + r;
            int grc = (gr < N_NODES) ? gr : (N_NODES - 1);
            float4 v = *(const float4*)(asrc + (size_t)grc * D + kbase + kq);
            As[kq + 0][r] = v.x;
            As[kq + 1][r] = v.y;
            As[kq + 2][r] = v.z;
            As[kq + 3][r] = v.w;
        }
#pragma unroll
        for (int p = 0; p < 2; p++) {
            int idx = tid + p * 256;
            int k = idx >> 5;
            int j = (idx & 31) * 4;
            *(float4*)&Bs[k][j] = *(const float4*)(wt + (size_t)(kt + k) * 128 + j);
        }
        __syncthreads();

#pragma unroll
        for (int k = 0; k < 16; k++) {
            float4 a0 = *(const float4*)&As[k][rowg];
            float4 a1 = *(const float4*)&As[k][rowg + 4];
            float4 b0 = *(const float4*)&Bs[k][colg];
            float4 b1 = *(const float4*)&Bs[k][colg + 4];
            float a[8] = {a0.x, a0.y, a0.z, a0.w, a1.x, a1.y, a1.z, a1.w};
            float b[8] = {b0.x, b0.y, b0.z, b0.w, b1.x, b1.y, b1.z, b1.w};
#pragma unroll
            for (int i = 0; i < 8; i++)
#pragma unroll
                for (int j = 0; j < 8; j++)
                    acc[i][j] += a[i] * b[j];
        }
        __syncthreads();
    }

    float bb[8];
#pragma unroll
    for (int j = 0; j < 8; j++) bb[j] = __ldg(bias + colg + j);
#pragma unroll
    for (int i = 0; i < 8; i++) {
        int gr = block_row0 + rowg + i;
        if (gr < N_NODES) {
            float4 o0, o1;
            o0.x = acc[i][0] + bb[0]; o0.y = acc[i][1] + bb[1];
            o0.z = acc[i][2] + bb[2]; o0.w = acc[i][3] + bb[3];
            o1.x = acc[i][4] + bb[4]; o1.y = acc[i][5] + bb[5];
            o1.z = acc[i][6] + bb[6]; o1.w = acc[i][7] + bb[7];
            *(float4*)(out + (size_t)gr * D + colg)     = o0;
            *(float4*)(out + (size_t)gr * D + colg + 4) = o1;
        }
    }
}

// ---------------------------------------------------------------------------
extern "C" void kernel_launch(void* const* d_in, const int* in_sizes, int n_in,
                              void* d_out, int out_size) {
    const float* x   = (const float*)d_in[0];
    const int*   ei  = (const int*)d_in[1];
    const float* Wl1 = (const float*)d_in[2];
    const float* bl1 = (const float*)d_in[3];
    const float* Wr1 = (const float*)d_in[4];
    const float* Wl2 = (const float*)d_in[5];
    const float* bl2 = (const float*)d_in[6];
    const float* Wr2 = (const float*)d_in[7];
    float* out = (float*)d_out;

    const int* src = ei;
    const int* dst = ei + E_EDGES;

    const int gather_blocks = (N_NODES * 32 + 255) / 256;

    cudaFuncSetAttribute(gemm_wmma_kernel, cudaFuncAttributeMaxDynamicSharedMemorySize, SM_TOTAL);

    // ---- CSR build + weight prep (shared across both layers) ----
    zero_deg_kernel<<<(N_NODES + 255) / 256, 256>>>();
    count_kernel<<<(E_EDGES + 511) / 512, 256>>>(dst);
    scan1_kernel<<<SCAN_NB, SCAN_BLK>>>();
    scan2_kernel<<<1, 64>>>();
    scan3_kernel<<<(N_NODES + 255) / 256, 256>>>();
    fill_kernel<<<(E_EDGES + 511) / 512, 256>>>(src, dst);
    prep_kernel<<<128, 256>>>(Wl1, Wr1, Wl2, Wr2);

    // ---- layer 1 ----
    gather_kernel<<<gather_blocks, 256>>>(x, 0);
    gemm_wmma_kernel<<<FULL_TILES, 256, SM_TOTAL>>>(x, bl1, nullptr, 0);
    gemm_tail_kernel<<<1, 256>>>(x, bl1, nullptr, 0);

    // ---- layer 2 ----
    gather_kernel<<<gather_blocks, 256>>>(x, 1);
    gemm_wmma_kernel<<<FULL_TILES, 256, SM_TOTAL>>>(x, bl2, out, 1);
    gemm_tail_kernel<<<1, 256>>>(x, bl2, out, 1);
}

// round 12
// speedup vs baseline: 1.6134x; 1.1303x over previous
#include <cuda_runtime.h>
#include <cuda_fp16.h>
#include <mma.h>
#include <cstdint>
#include <cstddef>

using namespace nvcuda;

#define N_NODES 50000
#define D 128
#define E_EDGES 800000
#define FULL_TILES (N_NODES / 128)                       // 390
#define TAIL_ROW0 (FULL_TILES * 128)                     // 49920
#define TAIL_ROWS (N_NODES - TAIL_ROW0)                  // 80

// wmma kernel shared layout (dynamic): A tile only
#define LDA 264                                          // 256 + 8 pad (halves)
#define SM_TOTAL (128 * LDA * 2)                         // 67584 (>= 128*128*4 for tail staging)

// Scratch (no allocations allowed in kernel_launch)
__device__ float  d_agg[(size_t)N_NODES * D];
__device__ float  d_h[(size_t)N_NODES * D];
__device__ int    d_deg[N_NODES];
__device__ int    d_rowptr[N_NODES + 1];
__device__ int    d_cursor[N_NODES + 1];
__device__ int    d_adj[E_EDGES];
__device__ __half d_wt1h[128 * 256];     // fp16 [n][k] (wmma B)
__device__ __half d_wt2h[128 * 256];
__device__ float  d_brep1[16 * 128];     // bias replicated 16 rows (accumulator init)
__device__ float  d_brep2[16 * 128];

// ---------------------------------------------------------------------------
// prep: zero degrees + fp16 weights [n][k] + replicated bias tiles
__global__ void prep_kernel(const float* __restrict__ Wl1, const float* __restrict__ Wr1,
                            const float* __restrict__ Wl2, const float* __restrict__ Wr2,
                            const float* __restrict__ bl1, const float* __restrict__ bl2) {
    int stride = gridDim.x * blockDim.x;
    int i0 = blockIdx.x * blockDim.x + threadIdx.x;
    for (int i = i0; i < 128 * 256; i += stride) {
        int n = i >> 8;          // 0..127
        int k = i & 255;         // 0..255
        float v1, v2;
        if (k < 128) {
            v1 = Wl1[n * 128 + k];
            v2 = Wl2[n * 128 + k];
        } else {
            v1 = Wr1[n * 128 + (k - 128)];
            v2 = Wr2[n * 128 + (k - 128)];
        }
        d_wt1h[i] = __float2half(v1);
        d_wt2h[i] = __float2half(v2);
    }
    for (int i = i0; i < N_NODES; i += stride) d_deg[i] = 0;
    for (int i = i0; i < 16 * 128; i += stride) {
        d_brep1[i] = bl1[i & 127];
        d_brep2[i] = bl2[i & 127];
    }
}

__global__ void count_kernel(const int* __restrict__ dst) {
    int stride = gridDim.x * blockDim.x;
    for (int e = blockIdx.x * blockDim.x + threadIdx.x; e < E_EDGES; e += stride) {
        atomicAdd(&d_deg[dst[e]], 1);
    }
}

// Whole prefix scan in ONE block (1024 threads, 49 chunks, carried offset).
// Writes rowptr[i+1] and cursor[i+1]; rowptr[0]=cursor[0]=0.
__global__ void __launch_bounds__(1024) scan_all_kernel() {
    __shared__ int wsum[32];
    __shared__ int carry_sh;
    int tid = threadIdx.x;
    int lane = tid & 31;
    int warp = tid >> 5;
    if (tid == 0) {
        carry_sh = 0;
        d_rowptr[0] = 0;
        d_cursor[0] = 0;
    }
    __syncthreads();

    const int CHUNKS = (N_NODES + 1023) / 1024;   // 49
    for (int it = 0; it < CHUNKS; it++) {
        int i = it * 1024 + tid;
        int v = (i < N_NODES) ? d_deg[i] : 0;
        int s = v;
#pragma unroll
        for (int off = 1; off < 32; off <<= 1) {
            int t = __shfl_up_sync(0xffffffffu, s, off);
            if (lane >= off) s += t;
        }
        if (lane == 31) wsum[warp] = s;
        __syncthreads();
        if (warp == 0) {
            int w = wsum[lane];
#pragma unroll
            for (int off = 1; off < 32; off <<= 1) {
                int t = __shfl_up_sync(0xffffffffu, w, off);
                if (lane >= off) w += t;
            }
            wsum[lane] = w;
        }
        __syncthreads();
        int incl = s + (warp > 0 ? wsum[warp - 1] : 0) + carry_sh;
        if (i < N_NODES) {
            d_rowptr[i + 1] = incl;
            d_cursor[i + 1] = incl;
        }
        __syncthreads();                 // everyone has read carry_sh
        if (tid == 1023) carry_sh = incl;
        __syncthreads();
    }
}

__global__ void fill_kernel(const int* __restrict__ src, const int* __restrict__ dst) {
    int stride = gridDim.x * blockDim.x;
    for (int e = blockIdx.x * blockDim.x + threadIdx.x; e < E_EDGES; e += stride) {
        int d = dst[e];
        int p = atomicAdd(&d_cursor[d], 1);
        d_adj[p] = src[e];
    }
}

// One warp per node: sum neighbor fp32 rows, scale by 1/deg, store (R7/R10-proven).
__global__ void __launch_bounds__(256) gather_kernel(const float* __restrict__ x, int layer) {
    const float* __restrict__ xin = (layer == 0) ? x : d_h;
    int gid = blockIdx.x * blockDim.x + threadIdx.x;
    int n = gid >> 5;
    if (n >= N_NODES) return;
    int lane = gid & 31;
    int base = d_rowptr[n];
    int end  = d_rowptr[n + 1];
    int deg  = end - base;
    size_t feat = (size_t)lane * 4;

    float4 acc = make_float4(0.f, 0.f, 0.f, 0.f);
    for (int i = base; i < end; i += 32) {
        int cnt = min(32, end - i);
        int sidx = (lane < cnt) ? __ldg(d_adj + i + lane) : 0;
        int j = 0;
        for (; j + 4 <= cnt; j += 4) {
            int s0 = __shfl_sync(0xffffffffu, sidx, j);
            int s1 = __shfl_sync(0xffffffffu, sidx, j + 1);
            int s2 = __shfl_sync(0xffffffffu, sidx, j + 2);
            int s3 = __shfl_sync(0xffffffffu, sidx, j + 3);
            float4 v0 = *(const float4*)(xin + (size_t)s0 * D + feat);
            float4 v1 = *(const float4*)(xin + (size_t)s1 * D + feat);
            float4 v2 = *(const float4*)(xin + (size_t)s2 * D + feat);
            float4 v3 = *(const float4*)(xin + (size_t)s3 * D + feat);
            acc.x += (v0.x + v1.x) + (v2.x + v3.x);
            acc.y += (v0.y + v1.y) + (v2.y + v3.y);
            acc.z += (v0.z + v1.z) + (v2.z + v3.z);
            acc.w += (v0.w + v1.w) + (v2.w + v3.w);
        }
        for (; j < cnt; j++) {
            int s = __shfl_sync(0xffffffffu, sidx, j);
            float4 v = *(const float4*)(xin + (size_t)s * D + feat);
            acc.x += v.x; acc.y += v.y; acc.z += v.z; acc.w += v.w;
        }
    }
    float sc = 1.0f / fmaxf((float)deg, 1.0f);
    acc.x *= sc; acc.y *= sc; acc.z *= sc; acc.w *= sc;
    *(float4*)(d_agg + (size_t)n * D + feat) = acc;
}

// ---------------------------------------------------------------------------
// Unified wmma fp16 GEMM, 391 blocks: D[128,128] = Ah[128,256] @ Bh[128,256]^T + bias
// A staged fp32->fp16 in shared; B fragments straight from global (L1-resident);
// bias via accumulator init from replicated global tile; block 390 = guarded tail.
__global__ void __launch_bounds__(256) gemm_wmma_kernel(const float* __restrict__ x,
                                                        float* __restrict__ outp,
                                                        int layer) {
    extern __shared__ char smem[];
    const float* __restrict__ xin  = (layer == 0) ? x : d_h;
    float* __restrict__ out        = (layer == 0) ? d_h : outp;
    const __half* __restrict__ wth = (layer == 0) ? d_wt1h : d_wt2h;
    const float* __restrict__ brep = (layer == 0) ? d_brep1 : d_brep2;

    __half (*As)[LDA] = (__half(*)[LDA])smem;

    int tid = threadIdx.x;
    int wid = tid >> 5;
    int warp_m = (wid & 3) * 32;     // 0,32,64,96
    int warp_n = (wid >> 2) * 64;    // 0,64
    int block_row0 = blockIdx.x * 128;

    // ---- stage A: fp32 [agg|xin] -> fp16 shared (row clamp covers tail) ----
    for (int idx = tid; idx < 128 * 64; idx += 256) {
        int m = idx >> 6;
        int kq = (idx & 63) * 4;
        int gr = block_row0 + m;
        int grc = (gr < N_NODES) ? gr : (N_NODES - 1);
        const float* srcp = (kq < 128) ? (d_agg + (size_t)grc * D + kq)
                                       : (xin + (size_t)grc * D + (kq - 128));
        float4 v = *(const float4*)srcp;
        __half2 p0 = __floats2half2_rn(v.x, v.y);
        __half2 p1 = __floats2half2_rn(v.z, v.w);
        uint2 u;
        u.x = *(uint32_t*)&p0;
        u.y = *(uint32_t*)&p1;
        *(uint2*)&As[m][kq] = u;
    }
    __syncthreads();

    // ---- accumulators initialized to bias (from replicated global tile) ----
    wmma::fragment<wmma::accumulator, 16, 16, 16, float> c[2][4];
#pragma unroll
    for (int i = 0; i < 2; i++)
#pragma unroll
        for (int j = 0; j < 4; j++)
            wmma::load_matrix_sync(c[i][j], brep + warp_n + j * 16, 128,
                                   wmma::mem_row_major);

    // ---- mainloop: 16 k-steps, A from shared, B from global ----
#pragma unroll
    for (int k0 = 0; k0 < 256; k0 += 16) {
        wmma::fragment<wmma::matrix_a, 16, 16, 16, __half, wmma::row_major> a[2];
        wmma::fragment<wmma::matrix_b, 16, 16, 16, __half, wmma::col_major> b[4];
#pragma unroll
        for (int i = 0; i < 2; i++)
            wmma::load_matrix_sync(a[i], &As[warp_m + i * 16][k0], LDA);
#pragma unroll
        for (int j = 0; j < 4; j++)
            wmma::load_matrix_sync(b[j], wth + (size_t)(warp_n + j * 16) * 256 + k0, 256);
#pragma unroll
        for (int i = 0; i < 2; i++)
#pragma unroll
            for (int j = 0; j < 4; j++)
                wmma::mma_sync(c[i][j], a[i], b[j], c[i][j]);
    }

    if (blockIdx.x < FULL_TILES) {
        // full tile: direct store
#pragma unroll
        for (int i = 0; i < 2; i++)
#pragma unroll
            for (int j = 0; j < 4; j++)
                wmma::store_matrix_sync(
                    out + (size_t)(block_row0 + warp_m + i * 16) * D + warp_n + j * 16,
                    c[i][j], D, wmma::mem_row_major);
    } else {
        // tail: stage through shared (reusing A space), guarded copy
        __syncthreads();             // done reading As
        float* stg = (float*)smem;   // 128x128 floats = 64KB <= 67.5KB
#pragma unroll
        for (int i = 0; i < 2; i++)
#pragma unroll
            for (int j = 0; j < 4; j++)
                wmma::store_matrix_sync(stg + (size_t)(warp_m + i * 16) * 128 + warp_n + j * 16,
                                        c[i][j], 128, wmma::mem_row_major);
        __syncthreads();
        for (int idx = tid; idx < TAIL_ROWS * 32; idx += 256) {
            int r = idx >> 5;
            int cq = (idx & 31) * 4;
            float4 v = *(float4*)(stg + r * 128 + cq);
            *(float4*)(out + (size_t)(TAIL_ROW0 + r) * D + cq) = v;
        }
    }
}

// ---------------------------------------------------------------------------
extern "C" void kernel_launch(void* const* d_in, const int* in_sizes, int n_in,
                              void* d_out, int out_size) {
    const float* x   = (const float*)d_in[0];
    const int*   ei  = (const int*)d_in[1];
    const float* Wl1 = (const float*)d_in[2];
    const float* bl1 = (const float*)d_in[3];
    const float* Wr1 = (const float*)d_in[4];
    const float* Wl2 = (const float*)d_in[5];
    const float* bl2 = (const float*)d_in[6];
    const float* Wr2 = (const float*)d_in[7];
    float* out = (float*)d_out;

    const int* src = ei;
    const int* dst = ei + E_EDGES;

    const int gather_blocks = (N_NODES * 32 + 255) / 256;

    cudaFuncSetAttribute(gemm_wmma_kernel, cudaFuncAttributeMaxDynamicSharedMemorySize, SM_TOTAL);

    // ---- CSR build + weight/bias prep (shared across both layers) ----
    prep_kernel<<<256, 256>>>(Wl1, Wr1, Wl2, Wr2, bl1, bl2);
    count_kernel<<<(E_EDGES + 511) / 512, 256>>>(dst);
    scan_all_kernel<<<1, 1024>>>();
    fill_kernel<<<(E_EDGES + 511) / 512, 256>>>(src, dst);

    // ---- layer 1 ----
    gather_kernel<<<gather_blocks, 256>>>(x, 0);
    gemm_wmma_kernel<<<FULL_TILES + 1, 256, SM_TOTAL>>>(x, nullptr, 0);

    // ---- layer 2 ----
    gather_kernel<<<gather_blocks, 256>>>(x, 1);
    gemm_wmma_kernel<<<FULL_TILES + 1, 256, SM_TOTAL>>>(x, out, 1);
}